// round 6
// baseline (speedup 1.0000x reference)
#include <cuda_runtime.h>
#include <cuda_bf16.h>
#include <cstdint>

#define R_TOTAL 32768   // B*N rows
#define KCODES  8192
#define DDIM    512
#define NTILES  512     // 16-wide code tiles for screening
#define MARGIN  5e-4f

// ---------------- static scratch (no allocations allowed) ----------------
__device__ float         g_rowA[R_TOTAL];
__device__ float         g_enorm[KCODES];
__device__ float         g_rowpart[R_TOTAL];
__device__ int           g_codes[R_TOTAL];
__device__ __nv_bfloat16 g_zb[(size_t)R_TOTAL * DDIM];   // 32 MB
__device__ __nv_bfloat16 g_eb[(size_t)KCODES * DDIM];    //  8 MB
__device__ float         g_eT[(size_t)DDIM * KCODES];    // 16 MB  embed^T [k][code]
__device__ float         g_tilemin[(size_t)R_TOTAL * NTILES]; // 64 MB

__device__ __forceinline__ uint32_t smaddr(const void* p) {
    return (uint32_t)__cvta_generic_to_shared(p);
}
#define CP16(dst, src) \
    asm volatile("cp.async.cg.shared.global [%0], [%1], 16;" :: "r"(dst), "l"(src))
#define CP_COMMIT() asm volatile("cp.async.commit_group;")

// ---------------------------------------------------------------------------
// Row sum-of-squares (reference-exact NEON 4-lane emulation), z + embed fused.
// ---------------------------------------------------------------------------
__global__ void rownorm_kernel(const float* __restrict__ z,
                               const float* __restrict__ embed) {
    int gid  = blockIdx.x * blockDim.x + threadIdx.x;
    int row  = gid >> 2;
    int lane = gid & 3;
    if (row >= R_TOTAL + KCODES) return;
    const float* p = (row < R_TOTAL) ? (z + (size_t)row * DDIM)
                                     : (embed + (size_t)(row - R_TOTAL) * DDIM);
    float acc = 0.0f;
    #pragma unroll 8
    for (int i = lane; i < DDIM; i += 4) {
        float v = p[i];
        acc = __fadd_rn(acc, __fmul_rn(v, v));
    }
    float o  = __shfl_xor_sync(0xFFFFFFFF, acc, 2);
    float s  = __fadd_rn(acc, o);
    float o2 = __shfl_xor_sync(0xFFFFFFFF, s, 1);
    float A  = __fadd_rn(s, o2);
    if (lane == 0) {
        if (row < R_TOTAL) g_rowA[row] = A;
        else               g_enorm[row - R_TOTAL] = A;
    }
}

// ---------------------------------------------------------------------------
// fp32 -> bf16 conversion of z and embed
// ---------------------------------------------------------------------------
__global__ void convert_kernel(const float* __restrict__ z,
                               const float* __restrict__ embed) {
    const int NZ = R_TOTAL * DDIM / 4;
    const int NE = KCODES * DDIM / 4;
    int i = blockIdx.x * blockDim.x + threadIdx.x;
    if (i < NZ) {
        float4 v = ((const float4*)z)[i];
        ((__nv_bfloat162*)g_zb)[i * 2 + 0] = __floats2bfloat162_rn(v.x, v.y);
        ((__nv_bfloat162*)g_zb)[i * 2 + 1] = __floats2bfloat162_rn(v.z, v.w);
    } else if (i < NZ + NE) {
        int j = i - NZ;
        float4 v = ((const float4*)embed)[j];
        ((__nv_bfloat162*)g_eb)[j * 2 + 0] = __floats2bfloat162_rn(v.x, v.y);
        ((__nv_bfloat162*)g_eb)[j * 2 + 1] = __floats2bfloat162_rn(v.z, v.w);
    }
}

// ---------------------------------------------------------------------------
// embed (8192 x 512) -> embed_T (512 x 8192), fp32, smem tiled
// ---------------------------------------------------------------------------
__global__ void transpose_kernel(const float* __restrict__ embed) {
    __shared__ float t[32][33];
    const int bx = blockIdx.x * 32;   // k
    const int by = blockIdx.y * 32;   // code
    const int x = threadIdx.x, y = threadIdx.y;   // 32 x 8
    #pragma unroll
    for (int i = 0; i < 32; i += 8)
        t[y + i][x] = embed[(size_t)(by + y + i) * DDIM + bx + x];
    __syncthreads();
    #pragma unroll
    for (int i = 0; i < 32; i += 8)
        g_eT[(size_t)(bx + y + i) * KCODES + by + x] = t[x][y + i];
}

// ---------------------------------------------------------------------------
// Screening GEMM: bf16 mma.sync m16n8k16. CTA tile 128x256, warp tile 64x64
// (8 warps: 2 row groups x 4 col groups), GBK=32 bf16, 3-stage cp.async
// pipeline, one __syncthreads per kt. Epilogue: per-(row, 16-code tile) min.
// Stage layout: A[128 rows][80 B] then B[256 rows][80 B]; 80-B row stride
// gives conflict-free ldmatrix phases.
// ---------------------------------------------------------------------------
#define GBK       32                  // bf16 elements per chunk (64 B)
#define NKT       (DDIM / GBK)        // 16
#define ROWST     80
#define A_BYTES   (128 * ROWST)       // 10240
#define B_BYTES   (256 * ROWST)       // 20480
#define STAGE_B   (A_BYTES + B_BYTES) // 30720
#define NSTAGE    3
#define SM_TOTAL  (NSTAGE * STAGE_B)  // 92160

__global__ void __launch_bounds__(256, 1) screen_gemm_kernel() {
    extern __shared__ __align__(128) char sm[];

    const int tid   = threadIdx.x;
    const int wid   = tid >> 5;
    const int lane  = tid & 31;
    const int warpY = wid & 1;    // 0..1 : 64-row group
    const int warpX = wid >> 1;   // 0..3 : 64-col group
    const int row0  = blockIdx.x * 128;
    const int n0    = blockIdx.y * 256;

    float acc[4][8][4];
    #pragma unroll
    for (int m = 0; m < 4; m++)
        #pragma unroll
        for (int n = 0; n < 8; n++)
            #pragma unroll
            for (int p = 0; p < 4; p++) acc[m][n][p] = 0.0f;

    // gmem->smem: A = 512 16-B chunks, B = 1024; thread does 6 chunks.
    // u=0,1 -> A chunks (tid + u*256); u=2..5 -> B chunks (tid + (u-2)*256).
    const __nv_bfloat16* zsrc = g_zb + (size_t)row0 * DDIM;
    const __nv_bfloat16* esrc = g_eb + (size_t)n0 * DDIM;
    const int ca0 = tid,        ra0 = ca0 >> 2, ha0 = (ca0 & 3) * 8;
    const int ca1 = tid + 256,  ra1 = ca1 >> 2, ha1 = (ca1 & 3) * 8;

#define LOAD_TILE(kt) do {                                                     \
    int st_ = (kt) % NSTAGE;                                                   \
    int k0_ = (kt) * GBK;                                                      \
    uint32_t ab = smaddr(sm + st_ * STAGE_B);                                  \
    CP16(ab + ra0 * ROWST + ha0 * 2, zsrc + (size_t)ra0 * DDIM + k0_ + ha0);   \
    CP16(ab + ra1 * ROWST + ha1 * 2, zsrc + (size_t)ra1 * DDIM + k0_ + ha1);   \
    _Pragma("unroll")                                                          \
    for (int u = 0; u < 4; u++) {                                              \
        int cb = tid + u * 256;                                                \
        int rb = cb >> 2, hb = (cb & 3) * 8;                                   \
        CP16(ab + A_BYTES + rb * ROWST + hb * 2,                               \
             esrc + (size_t)rb * DDIM + k0_ + hb);                             \
    }                                                                          \
    CP_COMMIT();                                                               \
} while (0)

    // ldmatrix addressing (byte units)
    const int i8 = lane & 7, q = lane >> 3;
    const int a_row  = warpY * 64 + (q & 1) * 8 + i8;   // + m*16
    const int a_colb = (q >> 1) * 16;                   // + ks*32
    const int b_row  = warpX * 64 + (q >> 1) * 8 + i8;  // + pr*16
    const int b_colb = (q & 1) * 16;                    // + ks*32

    LOAD_TILE(0);
    LOAD_TILE(1);

    #pragma unroll 1
    for (int kt = 0; kt < NKT; kt++) {
        if (kt < NKT - 1) asm volatile("cp.async.wait_group 1;");
        else              asm volatile("cp.async.wait_group 0;");
        __syncthreads();
        if (kt + 2 < NKT) LOAD_TILE(kt + 2);   // stage (kt-1)%3: consumed, safe

        const uint32_t abase = smaddr(sm + (kt % NSTAGE) * STAGE_B);
        #pragma unroll
        for (int ks = 0; ks < 2; ks++) {
            uint32_t a[4][4], b[4][4];
            #pragma unroll
            for (int m = 0; m < 4; m++) {
                uint32_t addr = abase + (uint32_t)(a_row + m * 16) * ROWST
                              + ks * 32 + a_colb;
                asm volatile("ldmatrix.sync.aligned.m8n8.x4.shared.b16 {%0,%1,%2,%3}, [%4];"
                    : "=r"(a[m][0]), "=r"(a[m][1]), "=r"(a[m][2]), "=r"(a[m][3])
                    : "r"(addr));
            }
            #pragma unroll
            for (int pr = 0; pr < 4; pr++) {
                uint32_t addr = abase + A_BYTES
                              + (uint32_t)(b_row + pr * 16) * ROWST
                              + ks * 32 + b_colb;
                asm volatile("ldmatrix.sync.aligned.m8n8.x4.shared.b16 {%0,%1,%2,%3}, [%4];"
                    : "=r"(b[pr][0]), "=r"(b[pr][1]), "=r"(b[pr][2]), "=r"(b[pr][3])
                    : "r"(addr));
            }
            #pragma unroll
            for (int m = 0; m < 4; m++)
                #pragma unroll
                for (int n = 0; n < 8; n++) {
                    const int pr = n >> 1, ro = (n & 1) * 2;
                    asm volatile(
                        "mma.sync.aligned.m16n8k16.row.col.f32.bf16.bf16.f32 "
                        "{%0,%1,%2,%3}, {%4,%5,%6,%7}, {%8,%9}, {%0,%1,%2,%3};"
                        : "+f"(acc[m][n][0]), "+f"(acc[m][n][1]),
                          "+f"(acc[m][n][2]), "+f"(acc[m][n][3])
                        : "r"(a[m][0]), "r"(a[m][1]), "r"(a[m][2]), "r"(a[m][3]),
                          "r"(b[pr][ro]), "r"(b[pr][ro + 1]));
                }
        }
    }
#undef LOAD_TILE

    // ---- epilogue: approx dist + per-(row, 16-code subtile) min ----
    const int g  = lane >> 2;   // row group 0..7
    const int qc = lane & 3;    // col pair

    float en[8][2];
    #pragma unroll
    for (int n = 0; n < 8; n++) {
        int col = n0 + warpX * 64 + n * 8 + qc * 2;
        en[n][0] = g_enorm[col];
        en[n][1] = g_enorm[col + 1];
    }

    #pragma unroll
    for (int m = 0; m < 4; m++) {
        #pragma unroll
        for (int h = 0; h < 2; h++) {
            int grow = row0 + warpY * 64 + m * 16 + g + h * 8;
            float Ar = g_rowA[grow];
            #pragma unroll
            for (int s = 0; s < 4; s++) {
                float v = 3.402823466e+38f;
                #pragma unroll
                for (int nn = 0; nn < 2; nn++) {
                    int n = s * 2 + nn;
                    #pragma unroll
                    for (int p = 0; p < 2; p++) {
                        float d = Ar - 2.0f * acc[m][n][h * 2 + p] + en[n][p];
                        v = fminf(v, d);
                    }
                }
                v = fminf(v, __shfl_xor_sync(0xFFFFFFFF, v, 1));
                v = fminf(v, __shfl_xor_sync(0xFFFFFFFF, v, 2));
                if (qc == 0)
                    g_tilemin[(size_t)grow * NTILES + blockIdx.y * 16 + warpX * 4 + s] = v;
            }
        }
    }
}

// ---------------------------------------------------------------------------
// Rescore: candidate tiles within MARGIN, recomputed bit-exactly via the
// TRANSPOSED codebook (16 consecutive codes per tile -> 64 B contiguous per k).
// One warp per row; half-warps process alternating candidate tiles.
// ---------------------------------------------------------------------------
__global__ void __launch_bounds__(256) rescore_kernel(
    const float* __restrict__ z,
    float* __restrict__ codes_f)
{
    __shared__ float zs[8][DDIM];
    __shared__ int   cand[8][64];
    const int wid  = threadIdx.x >> 5;
    const int lane = threadIdx.x & 31;
    const int row  = blockIdx.x * 8 + wid;

    {
        const float4* z4 = (const float4*)(z + (size_t)row * DDIM);
        float4* s4 = (float4*)zs[wid];
        #pragma unroll
        for (int i = lane; i < DDIM / 4; i += 32) s4[i] = z4[i];
    }

    float tm[16];
    #pragma unroll
    for (int j = 0; j < 16; j++)
        tm[j] = g_tilemin[(size_t)row * NTILES + lane + 32 * j];

    float rmin = tm[0];
    #pragma unroll
    for (int j = 1; j < 16; j++) rmin = fminf(rmin, tm[j]);
    #pragma unroll
    for (int o = 16; o > 0; o >>= 1)
        rmin = fminf(rmin, __shfl_xor_sync(0xFFFFFFFF, rmin, o));

    const float thr = rmin + MARGIN;
    int cnt = 0;
    #pragma unroll
    for (int j = 0; j < 16; j++) {
        unsigned mask = __ballot_sync(0xFFFFFFFF, tm[j] <= thr);
        if ((mask >> lane) & 1) {
            int pos = cnt + __popc(mask & ((1u << lane) - 1));
            if (pos < 64) cand[wid][pos] = lane + 32 * j;
        }
        cnt += __popc(mask);
    }
    if (cnt > 64) cnt = 64;
    __syncwarp();

    const float A    = g_rowA[row];
    const int   half = lane >> 4;
    const int   l16  = lane & 15;
    const float* zr  = zs[wid];

    float bestv = 3.402823466e+38f;
    int   besti = 0x7FFFFFFF;

    for (int t = half; t < cnt; t += 2) {
        const int c = cand[wid][t] * 16 + l16;
        const float* ec = g_eT + c;
        float dot = 0.0f;
        #pragma unroll 8
        for (int k = 0; k < DDIM; k++)
            dot = fmaf(zr[k], ec[(size_t)k * KCODES], dot);
        float B2   = 2.0f * dot;
        float tt   = __fadd_rn(A, -B2);
        float dist = __fadd_rn(tt, g_enorm[c]);
        if (dist < bestv || (dist == bestv && c < besti)) {
            bestv = dist;
            besti = c;
        }
    }

    #pragma unroll
    for (int o = 16; o > 0; o >>= 1) {
        float ov = __shfl_xor_sync(0xFFFFFFFF, bestv, o);
        int   oi = __shfl_xor_sync(0xFFFFFFFF, besti, o);
        if (ov < bestv || (ov == bestv && oi < besti)) { bestv = ov; besti = oi; }
    }
    if (lane == 0) {
        g_codes[row] = besti;
        if (codes_f) codes_f[row] = (float)besti;
    }
}

// ---------------------------------------------------------------------------
// Gather + loss (unchanged, proven)
// ---------------------------------------------------------------------------
__global__ void gather_kernel(const float* __restrict__ z,
                              const float* __restrict__ embed,
                              float* __restrict__ out_zq) {
    const int row = blockIdx.x;
    const int t   = threadIdx.x;
    const int c   = g_codes[row];
    float4 e  = *(const float4*)(embed + (size_t)c * DDIM + t * 4);
    float4 zz = *(const float4*)(z + (size_t)row * DDIM + t * 4);
    *(float4*)(out_zq + (size_t)row * DDIM + t * 4) = e;
    float dx = zz.x - e.x, dy = zz.y - e.y, dz = zz.z - e.z, dw = zz.w - e.w;
    float s = dx * dx + dy * dy + dz * dz + dw * dw;
    __shared__ float red[128];
    red[t] = s;
    __syncthreads();
    #pragma unroll
    for (int o = 64; o > 0; o >>= 1) {
        if (t < o) red[t] += red[t + o];
        __syncthreads();
    }
    if (t == 0) g_rowpart[row] = red[0];
}

__global__ void loss_kernel(float* __restrict__ out_loss) {
    const int t = threadIdx.x;
    float s = 0.0f;
    for (int i = t; i < R_TOTAL; i += 1024) s += g_rowpart[i];
    __shared__ float red[1024];
    red[t] = s;
    __syncthreads();
    for (int o = 512; o > 0; o >>= 1) {
        if (t < o) red[t] += red[t + o];
        __syncthreads();
    }
    if (t == 0) out_loss[0] = 0.1f * (red[0] / 16777216.0f);
}

// ---------------------------------------------------------------------------
extern "C" void kernel_launch(void* const* d_in, const int* in_sizes, int n_in,
                              void* d_out, int out_size) {
    const float* z     = (const float*)d_in[0];   // (8,4096,512) f32
    const float* embed = (const float*)d_in[1];   // (8192,512) f32
    float* out = (float*)d_out;

    const long long ZQ_ELEMS = (long long)R_TOTAL * DDIM;
    float* out_zq    = out;
    float* out_codes = 0;
    float* out_loss  = 0;
    if ((long long)out_size >= ZQ_ELEMS + R_TOTAL + 1) {
        out_codes = out + ZQ_ELEMS;
        out_loss  = out + ZQ_ELEMS + R_TOTAL;
    }

    static int init_done = 0;
    if (!init_done) {
        cudaFuncSetAttribute(screen_gemm_kernel,
                             cudaFuncAttributeMaxDynamicSharedMemorySize, SM_TOTAL);
        init_done = 1;
    }

    const int NCONV = (R_TOTAL * DDIM + KCODES * DDIM) / 4;
    convert_kernel<<<(NCONV + 255) / 256, 256>>>(z, embed);

    rownorm_kernel<<<((R_TOTAL + KCODES) * 4 + 255) / 256, 256>>>(z, embed);

    transpose_kernel<<<dim3(DDIM / 32, KCODES / 32), dim3(32, 8)>>>(embed);

    dim3 gg(R_TOTAL / 128, KCODES / 256);   // (256, 32)
    screen_gemm_kernel<<<gg, 256, SM_TOTAL>>>();

    rescore_kernel<<<R_TOTAL / 8, 256>>>(z, out_codes);

    gather_kernel<<<R_TOTAL, 128>>>(z, embed, out_zq);

    if (out_loss) loss_kernel<<<1, 1024>>>(out_loss);
}

// round 7
// speedup vs baseline: 1.1954x; 1.1954x over previous
#include <cuda_runtime.h>
#include <cuda_bf16.h>
#include <cstdint>

#define R_TOTAL 32768   // B*N rows
#define KCODES  8192
#define DDIM    512
#define NTILES  512     // 16-wide code tiles for screening
#define MARGIN  2.5e-4f

// ---------------- static scratch (no allocations allowed) ----------------
__device__ float         g_rowA[R_TOTAL];
__device__ float         g_enorm[KCODES];
__device__ float         g_rowpart[R_TOTAL];
__device__ int           g_codes[R_TOTAL];
__device__ __nv_bfloat16 g_zb[(size_t)R_TOTAL * DDIM];   // 32 MB
__device__ __nv_bfloat16 g_eb[(size_t)KCODES * DDIM];    //  8 MB
__device__ float         g_eT[(size_t)DDIM * KCODES];    // 16 MB  embed^T [k][code]
__device__ float         g_tilemin[(size_t)R_TOTAL * NTILES]; // 64 MB

__device__ __forceinline__ uint32_t smaddr(const void* p) {
    return (uint32_t)__cvta_generic_to_shared(p);
}
#define CP16(dst, src) \
    asm volatile("cp.async.cg.shared.global [%0], [%1], 16;" :: "r"(dst), "l"(src))
#define CP_COMMIT() asm volatile("cp.async.commit_group;")

// ---------------------------------------------------------------------------
// Row sum-of-squares (reference-exact NEON 4-lane emulation), z + embed fused.
// ---------------------------------------------------------------------------
__global__ void rownorm_kernel(const float* __restrict__ z,
                               const float* __restrict__ embed) {
    int gid  = blockIdx.x * blockDim.x + threadIdx.x;
    int row  = gid >> 2;
    int lane = gid & 3;
    if (row >= R_TOTAL + KCODES) return;
    const float* p = (row < R_TOTAL) ? (z + (size_t)row * DDIM)
                                     : (embed + (size_t)(row - R_TOTAL) * DDIM);
    float acc = 0.0f;
    #pragma unroll 8
    for (int i = lane; i < DDIM; i += 4) {
        float v = p[i];
        acc = __fadd_rn(acc, __fmul_rn(v, v));
    }
    float o  = __shfl_xor_sync(0xFFFFFFFF, acc, 2);
    float s  = __fadd_rn(acc, o);
    float o2 = __shfl_xor_sync(0xFFFFFFFF, s, 1);
    float A  = __fadd_rn(s, o2);
    if (lane == 0) {
        if (row < R_TOTAL) g_rowA[row] = A;
        else               g_enorm[row - R_TOTAL] = A;
    }
}

// ---------------------------------------------------------------------------
// fp32 -> bf16 conversion of z and embed
// ---------------------------------------------------------------------------
__global__ void convert_kernel(const float* __restrict__ z,
                               const float* __restrict__ embed) {
    const int NZ = R_TOTAL * DDIM / 4;
    const int NE = KCODES * DDIM / 4;
    int i = blockIdx.x * blockDim.x + threadIdx.x;
    if (i < NZ) {
        float4 v = ((const float4*)z)[i];
        ((__nv_bfloat162*)g_zb)[i * 2 + 0] = __floats2bfloat162_rn(v.x, v.y);
        ((__nv_bfloat162*)g_zb)[i * 2 + 1] = __floats2bfloat162_rn(v.z, v.w);
    } else if (i < NZ + NE) {
        int j = i - NZ;
        float4 v = ((const float4*)embed)[j];
        ((__nv_bfloat162*)g_eb)[j * 2 + 0] = __floats2bfloat162_rn(v.x, v.y);
        ((__nv_bfloat162*)g_eb)[j * 2 + 1] = __floats2bfloat162_rn(v.z, v.w);
    }
}

// ---------------------------------------------------------------------------
// embed (8192 x 512) -> embed_T (512 x 8192), fp32, smem tiled
// ---------------------------------------------------------------------------
__global__ void transpose_kernel(const float* __restrict__ embed) {
    __shared__ float t[32][33];
    const int bx = blockIdx.x * 32;   // k
    const int by = blockIdx.y * 32;   // code
    const int x = threadIdx.x, y = threadIdx.y;   // 32 x 8
    #pragma unroll
    for (int i = 0; i < 32; i += 8)
        t[y + i][x] = embed[(size_t)(by + y + i) * DDIM + bx + x];
    __syncthreads();
    #pragma unroll
    for (int i = 0; i < 32; i += 8)
        g_eT[(size_t)(bx + y + i) * KCODES + by + x] = t[x][y + i];
}

// ---------------------------------------------------------------------------
// Screening GEMM: bf16 mma.sync m16n8k16. CTA = 128 threads (4 warps, 2x2),
// CTA tile 128x128, warp tile 64x64. GBK=32, 3-stage cp.async pipeline,
// one __syncthreads per kt; 2 CTAs/SM so barriers interleave across CTAs.
// Epilogue: per-(row, 16-code tile) min of approx dist -> g_tilemin.
// Stage layout: A[128 rows][80 B] then B[128 rows][80 B] (conflict-free).
// ---------------------------------------------------------------------------
#define GBK       32                  // bf16 elements per chunk (64 B)
#define NKT       (DDIM / GBK)        // 16
#define ROWST     80
#define HALF_ST   (128 * ROWST)       // 10240
#define STAGE_B   (2 * HALF_ST)       // 20480
#define NSTAGE    3
#define SM_TOTAL  (NSTAGE * STAGE_B)  // 61440

__global__ void __launch_bounds__(128, 2) screen_gemm_kernel() {
    extern __shared__ __align__(128) char sm[];

    const int tid   = threadIdx.x;
    const int wid   = tid >> 5;
    const int lane  = tid & 31;
    const int warpY = wid & 1;    // 0..1 : 64-row group
    const int warpX = wid >> 1;   // 0..1 : 64-col group
    const int row0  = blockIdx.x * 128;
    const int n0    = blockIdx.y * 128;

    float acc[4][8][4];
    #pragma unroll
    for (int m = 0; m < 4; m++)
        #pragma unroll
        for (int n = 0; n < 8; n++)
            #pragma unroll
            for (int p = 0; p < 4; p++) acc[m][n][p] = 0.0f;

    // gmem->smem: A and B each 512 16-B chunks per stage; thread does 4+4.
    const __nv_bfloat16* zsrc = g_zb + (size_t)row0 * DDIM;
    const __nv_bfloat16* esrc = g_eb + (size_t)n0 * DDIM;

#define LOAD_TILE(kt) do {                                                     \
    int st_ = (kt) % NSTAGE;                                                   \
    int k0_ = (kt) * GBK;                                                      \
    uint32_t ab = smaddr(sm + st_ * STAGE_B);                                  \
    _Pragma("unroll")                                                          \
    for (int u = 0; u < 4; u++) {                                              \
        int c = tid + u * 128;                                                 \
        int r = c >> 2, h = (c & 3) * 8;                                       \
        CP16(ab + r * ROWST + h * 2, zsrc + (size_t)r * DDIM + k0_ + h);       \
        CP16(ab + HALF_ST + r * ROWST + h * 2,                                 \
             esrc + (size_t)r * DDIM + k0_ + h);                               \
    }                                                                          \
    CP_COMMIT();                                                               \
} while (0)

    // ldmatrix addressing (byte units)
    const int i8 = lane & 7, q = lane >> 3;
    const int a_row  = warpY * 64 + (q & 1) * 8 + i8;   // + m*16
    const int a_colb = (q >> 1) * 16;                   // + ks*32
    const int b_row  = warpX * 64 + (q >> 1) * 8 + i8;  // + pr*16
    const int b_colb = (q & 1) * 16;                    // + ks*32

    LOAD_TILE(0);
    LOAD_TILE(1);

    #pragma unroll 1
    for (int kt = 0; kt < NKT; kt++) {
        if (kt < NKT - 1) asm volatile("cp.async.wait_group 1;");
        else              asm volatile("cp.async.wait_group 0;");
        __syncthreads();
        if (kt + 2 < NKT) LOAD_TILE(kt + 2);   // stage (kt-1)%3: consumed, safe

        const uint32_t abase = smaddr(sm + (kt % NSTAGE) * STAGE_B);
        #pragma unroll
        for (int ks = 0; ks < 2; ks++) {
            uint32_t a[4][4], b[4][4];
            #pragma unroll
            for (int m = 0; m < 4; m++) {
                uint32_t addr = abase + (uint32_t)(a_row + m * 16) * ROWST
                              + ks * 32 + a_colb;
                asm volatile("ldmatrix.sync.aligned.m8n8.x4.shared.b16 {%0,%1,%2,%3}, [%4];"
                    : "=r"(a[m][0]), "=r"(a[m][1]), "=r"(a[m][2]), "=r"(a[m][3])
                    : "r"(addr));
            }
            #pragma unroll
            for (int pr = 0; pr < 4; pr++) {
                uint32_t addr = abase + HALF_ST
                              + (uint32_t)(b_row + pr * 16) * ROWST
                              + ks * 32 + b_colb;
                asm volatile("ldmatrix.sync.aligned.m8n8.x4.shared.b16 {%0,%1,%2,%3}, [%4];"
                    : "=r"(b[pr][0]), "=r"(b[pr][1]), "=r"(b[pr][2]), "=r"(b[pr][3])
                    : "r"(addr));
            }
            #pragma unroll
            for (int m = 0; m < 4; m++)
                #pragma unroll
                for (int n = 0; n < 8; n++) {
                    const int pr = n >> 1, ro = (n & 1) * 2;
                    asm volatile(
                        "mma.sync.aligned.m16n8k16.row.col.f32.bf16.bf16.f32 "
                        "{%0,%1,%2,%3}, {%4,%5,%6,%7}, {%8,%9}, {%0,%1,%2,%3};"
                        : "+f"(acc[m][n][0]), "+f"(acc[m][n][1]),
                          "+f"(acc[m][n][2]), "+f"(acc[m][n][3])
                        : "r"(a[m][0]), "r"(a[m][1]), "r"(a[m][2]), "r"(a[m][3]),
                          "r"(b[pr][ro]), "r"(b[pr][ro + 1]));
                }
        }
    }
#undef LOAD_TILE

    // ---- epilogue: approx dist + per-(row, 16-code subtile) min ----
    const int g  = lane >> 2;   // row group 0..7
    const int qc = lane & 3;    // col pair

    float en[8][2];
    #pragma unroll
    for (int n = 0; n < 8; n++) {
        int col = n0 + warpX * 64 + n * 8 + qc * 2;
        en[n][0] = g_enorm[col];
        en[n][1] = g_enorm[col + 1];
    }

    #pragma unroll
    for (int m = 0; m < 4; m++) {
        #pragma unroll
        for (int h = 0; h < 2; h++) {
            int grow = row0 + warpY * 64 + m * 16 + g + h * 8;
            float Ar = g_rowA[grow];
            #pragma unroll
            for (int s = 0; s < 4; s++) {
                float v = 3.402823466e+38f;
                #pragma unroll
                for (int nn = 0; nn < 2; nn++) {
                    int n = s * 2 + nn;
                    #pragma unroll
                    for (int p = 0; p < 2; p++) {
                        float d = Ar - 2.0f * acc[m][n][h * 2 + p] + en[n][p];
                        v = fminf(v, d);
                    }
                }
                v = fminf(v, __shfl_xor_sync(0xFFFFFFFF, v, 1));
                v = fminf(v, __shfl_xor_sync(0xFFFFFFFF, v, 2));
                if (qc == 0)
                    g_tilemin[(size_t)grow * NTILES + blockIdx.y * 8 + warpX * 4 + s] = v;
            }
        }
    }
}

// ---------------------------------------------------------------------------
// Rescore: candidate tiles within MARGIN, recomputed bit-exactly via the
// TRANSPOSED codebook (16 consecutive codes per tile -> 64 B contiguous per k).
// One warp per row; half-warps process alternating candidate tiles.
// ---------------------------------------------------------------------------
__global__ void __launch_bounds__(256) rescore_kernel(
    const float* __restrict__ z,
    float* __restrict__ codes_f)
{
    __shared__ float zs[8][DDIM];
    __shared__ int   cand[8][64];
    const int wid  = threadIdx.x >> 5;
    const int lane = threadIdx.x & 31;
    const int row  = blockIdx.x * 8 + wid;

    {
        const float4* z4 = (const float4*)(z + (size_t)row * DDIM);
        float4* s4 = (float4*)zs[wid];
        #pragma unroll
        for (int i = lane; i < DDIM / 4; i += 32) s4[i] = z4[i];
    }

    float tm[16];
    #pragma unroll
    for (int j = 0; j < 16; j++)
        tm[j] = g_tilemin[(size_t)row * NTILES + lane + 32 * j];

    float rmin = tm[0];
    #pragma unroll
    for (int j = 1; j < 16; j++) rmin = fminf(rmin, tm[j]);
    #pragma unroll
    for (int o = 16; o > 0; o >>= 1)
        rmin = fminf(rmin, __shfl_xor_sync(0xFFFFFFFF, rmin, o));

    const float thr = rmin + MARGIN;
    int cnt = 0;
    #pragma unroll
    for (int j = 0; j < 16; j++) {
        unsigned mask = __ballot_sync(0xFFFFFFFF, tm[j] <= thr);
        if ((mask >> lane) & 1) {
            int pos = cnt + __popc(mask & ((1u << lane) - 1));
            if (pos < 64) cand[wid][pos] = lane + 32 * j;
        }
        cnt += __popc(mask);
    }
    if (cnt > 64) cnt = 64;
    __syncwarp();

    const float A    = g_rowA[row];
    const int   half = lane >> 4;
    const int   l16  = lane & 15;
    const float* zr  = zs[wid];

    float bestv = 3.402823466e+38f;
    int   besti = 0x7FFFFFFF;

    for (int t = half; t < cnt; t += 2) {
        const int c = cand[wid][t] * 16 + l16;
        const float* ec = g_eT + c;
        float dot = 0.0f;
        #pragma unroll 8
        for (int k = 0; k < DDIM; k++)
            dot = fmaf(zr[k], ec[(size_t)k * KCODES], dot);
        float B2   = 2.0f * dot;
        float tt   = __fadd_rn(A, -B2);
        float dist = __fadd_rn(tt, g_enorm[c]);
        if (dist < bestv || (dist == bestv && c < besti)) {
            bestv = dist;
            besti = c;
        }
    }

    #pragma unroll
    for (int o = 16; o > 0; o >>= 1) {
        float ov = __shfl_xor_sync(0xFFFFFFFF, bestv, o);
        int   oi = __shfl_xor_sync(0xFFFFFFFF, besti, o);
        if (ov < bestv || (ov == bestv && oi < besti)) { bestv = ov; besti = oi; }
    }
    if (lane == 0) {
        g_codes[row] = besti;
        if (codes_f) codes_f[row] = (float)besti;
    }
}

// ---------------------------------------------------------------------------
// Gather + loss (unchanged, proven)
// ---------------------------------------------------------------------------
__global__ void gather_kernel(const float* __restrict__ z,
                              const float* __restrict__ embed,
                              float* __restrict__ out_zq) {
    const int row = blockIdx.x;
    const int t   = threadIdx.x;
    const int c   = g_codes[row];
    float4 e  = *(const float4*)(embed + (size_t)c * DDIM + t * 4);
    float4 zz = *(const float4*)(z + (size_t)row * DDIM + t * 4);
    *(float4*)(out_zq + (size_t)row * DDIM + t * 4) = e;
    float dx = zz.x - e.x, dy = zz.y - e.y, dz = zz.z - e.z, dw = zz.w - e.w;
    float s = dx * dx + dy * dy + dz * dz + dw * dw;
    __shared__ float red[128];
    red[t] = s;
    __syncthreads();
    #pragma unroll
    for (int o = 64; o > 0; o >>= 1) {
        if (t < o) red[t] += red[t + o];
        __syncthreads();
    }
    if (t == 0) g_rowpart[row] = red[0];
}

__global__ void loss_kernel(float* __restrict__ out_loss) {
    const int t = threadIdx.x;
    float s = 0.0f;
    for (int i = t; i < R_TOTAL; i += 1024) s += g_rowpart[i];
    __shared__ float red[1024];
    red[t] = s;
    __syncthreads();
    for (int o = 512; o > 0; o >>= 1) {
        if (t < o) red[t] += red[t + o];
        __syncthreads();
    }
    if (t == 0) out_loss[0] = 0.1f * (red[0] / 16777216.0f);
}

// ---------------------------------------------------------------------------
extern "C" void kernel_launch(void* const* d_in, const int* in_sizes, int n_in,
                              void* d_out, int out_size) {
    const float* z     = (const float*)d_in[0];   // (8,4096,512) f32
    const float* embed = (const float*)d_in[1];   // (8192,512) f32
    float* out = (float*)d_out;

    const long long ZQ_ELEMS = (long long)R_TOTAL * DDIM;
    float* out_zq    = out;
    float* out_codes = 0;
    float* out_loss  = 0;
    if ((long long)out_size >= ZQ_ELEMS + R_TOTAL + 1) {
        out_codes = out + ZQ_ELEMS;
        out_loss  = out + ZQ_ELEMS + R_TOTAL;
    }

    static int init_done = 0;
    if (!init_done) {
        cudaFuncSetAttribute(screen_gemm_kernel,
                             cudaFuncAttributeMaxDynamicSharedMemorySize, SM_TOTAL);
        init_done = 1;
    }

    const int NCONV = (R_TOTAL * DDIM + KCODES * DDIM) / 4;
    convert_kernel<<<(NCONV + 255) / 256, 256>>>(z, embed);

    rownorm_kernel<<<((R_TOTAL + KCODES) * 4 + 255) / 256, 256>>>(z, embed);

    transpose_kernel<<<dim3(DDIM / 32, KCODES / 32), dim3(32, 8)>>>(embed);

    dim3 gg(R_TOTAL / 128, KCODES / 128);   // (256, 64)
    screen_gemm_kernel<<<gg, 128, SM_TOTAL>>>();

    rescore_kernel<<<R_TOTAL / 8, 256>>>(z, out_codes);

    gather_kernel<<<R_TOTAL, 128>>>(z, embed, out_zq);

    if (out_loss) loss_kernel<<<1, 1024>>>(out_loss);
}